// round 13
// baseline (speedup 1.0000x reference)
#include <cuda_runtime.h>
#include <cuda_bf16.h>
#include <math.h>
#include <stdint.h>

// ---------------- problem constants ----------------------------------------
#define E_TOTAL 600000
#define NDST    10000
#define DN      100
#define DE      172
#define DTF     100
#define DOUT    128
#define HEADS   2
#define KV_IN   372   // DN + DE + DTF
#define KPAD    384
#define OUT_IN  228   // DOUT + DN
#define MT      64    // edges per block in k_edge
#define NBLK    (E_TOTAL / MT)    // 9375
#define CHK     192   // k per chunk
#define NB      256   // MMA output cols: [K plane 0..127 | V plane 128..255]
#define PKA     200   // A smem pitch (bf16 elems)
#define SMEM_EDGE_BYTES (MT * PKA * 2 * 2)   // hi+lo planes = 51200 B

// ---------------- scratch (device globals) ---------------------------------
__device__ float g_qnodes[NDST * DOUT];
__device__ float g_qb[NDST * HEADS];  // fold of bk into Q
__device__ float g_z[NDST * HEADS];
__device__ float g_agg[NDST * DOUT];
// [wk | wv] transposed [n][k] split-bf16 (k padded to 384); n<128 = wk col,
// n>=128 = wv col (n-128)
__device__ __nv_bfloat16 g_BT_hi[NB * KPAD];
__device__ __nv_bfloat16 g_BT_lo[NB * KPAD];

// ---------------- mma.sync helper ------------------------------------------
__device__ __forceinline__ void mma16816(float* c, const uint32_t* a,
                                         const uint32_t* b) {
    asm volatile(
        "mma.sync.aligned.m16n8k16.row.col.f32.bf16.bf16.f32 "
        "{%0,%1,%2,%3}, {%4,%5,%6,%7}, {%8,%9}, {%0,%1,%2,%3};"
        : "+f"(c[0]), "+f"(c[1]), "+f"(c[2]), "+f"(c[3])
        : "r"(a[0]), "r"(a[1]), "r"(a[2]), "r"(a[3]), "r"(b[0]), "r"(b[1]));
}

__device__ __forceinline__ uint32_t bfpack(float v0, float v1) {
    __nv_bfloat16 h0 = __float2bfloat16(v0), h1 = __float2bfloat16(v1);
    return (uint32_t)__bfloat16_as_ushort(h0)
         | ((uint32_t)__bfloat16_as_ushort(h1) << 16);
}

// ---------------- init ------------------------------------------------------
__global__ void k_init() {
    int i = blockIdx.x * blockDim.x + threadIdx.x;
    int stride = gridDim.x * blockDim.x;
    for (int k = i; k < NDST * HEADS; k += stride) g_z[k] = 0.f;
    for (int k = i; k < NDST * DOUT; k += stride)  g_agg[k] = 0.f;
}

// ---------------- prep B: [wk|wv] -> transposed split-bf16 -----------------
__global__ void k_prepB(const float* __restrict__ wk, const float* __restrict__ wv) {
    int i = blockIdx.x * blockDim.x + threadIdx.x;
    if (i >= NB * KPAD) return;
    int n = i / KPAD, k = i % KPAD;
    float v = 0.f;
    if (k < KV_IN) v = (n < DOUT) ? wk[k * DOUT + n] : wv[k * DOUT + (n - DOUT)];
    __nv_bfloat16 hi = __float2bfloat16(v);
    g_BT_hi[i] = hi;
    g_BT_lo[i] = __float2bfloat16(v - __bfloat162float(hi));
}

// ---------------- Q per dst node -------------------------------------------
__global__ __launch_bounds__(128) void k_qnodes(
    const float* __restrict__ h, const float* __restrict__ wq,
    const float* __restrict__ bq, const float* __restrict__ time_b)
{
    int j  = threadIdx.x;
    int n0 = blockIdx.x * 4;
    __shared__ float sh[4][DN];
    for (int idx = j; idx < 4 * DN; idx += 128) {
        int n = idx / DN, i = idx % DN;
        sh[n][i] = h[(size_t)(n0 + n) * DN + i];
    }
    __syncthreads();
    float qc = bq[j];
    for (int i = 0; i < DTF; i++)
        qc = fmaf(wq[(DN + i) * DOUT + j], cosf(time_b[i]), qc);
    float a0 = qc, a1 = qc, a2 = qc, a3 = qc;
    for (int i = 0; i < DN; i++) {
        float w = wq[i * DOUT + j];
        a0 = fmaf(sh[0][i], w, a0);
        a1 = fmaf(sh[1][i], w, a1);
        a2 = fmaf(sh[2][i], w, a2);
        a3 = fmaf(sh[3][i], w, a3);
    }
    g_qnodes[(n0 + 0) * DOUT + j] = a0;
    g_qnodes[(n0 + 1) * DOUT + j] = a1;
    g_qnodes[(n0 + 2) * DOUT + j] = a2;
    g_qnodes[(n0 + 3) * DOUT + j] = a3;
}

// ---------------- fold bk into per-(dst,head) score constant ---------------
__global__ void k_qb(const float* __restrict__ bk) {
    int i = blockIdx.x * blockDim.x + threadIdx.x;
    if (i >= NDST * HEADS) return;
    int d = i >> 1, hh = i & 1;
    float s = 0.f;
    for (int j = 0; j < 64; j++)
        s = fmaf(g_qnodes[(size_t)d * DOUT + hh * 64 + j], bk[hh * 64 + j], s);
    g_qb[i] = s;
}

// ---------------- HMMA edge kernel -----------------------------------------
// [K|V][64x256] = X[64x384] * [wk|wv] via split-bf16 mma.sync (3 terms).
// Warps 0-3: K plane (scores via Q-gather epilogue); warps 4-7: V plane
// (weighted aggregation atomics). exp w/o max-sub; z/agg via L2 atomics.
__global__ __launch_bounds__(256, 2) void k_edge(
    const float* __restrict__ h,  const float* __restrict__ ef,
    const float* __restrict__ dt, const int*   __restrict__ dst_idx,
    const float* __restrict__ time_w, const float* __restrict__ time_b,
    const float* __restrict__ bv, const float* __restrict__ att_bias)
{
    extern __shared__ unsigned char dsm[];
    __nv_bfloat16* sAhi = (__nv_bfloat16*)dsm;               // [MT][PKA]
    __nv_bfloat16* sAlo = sAhi + MT * PKA;
    __shared__ int   s_dst[MT];
    __shared__ float s_dtv[MT];
    __shared__ float s_w[MT][HEADS];
    __shared__ float s_sc[MT][HEADS];
    __shared__ float s_ab[2];

    int t   = threadIdx.x;
    int e0  = blockIdx.x * MT;
    int wid = t >> 5, lane = t & 31;
    int g   = lane >> 2, tq = lane & 3;
    int nb  = wid * 32;          // B row base (K plane wid<4, V plane wid>=4)

    if (t < MT) { s_dst[t] = dst_idx[e0 + t]; s_dtv[t] = dt[e0 + t]; }
    if (t < MT * HEADS) ((float*)s_sc)[t] = 0.f;
    if (t < 2) {
        float s = 0.f;
        #pragma unroll 8
        for (int i = 0; i < 64; i++) s += att_bias[t * 64 + i];
        s_ab[t] = s;
    }
    __syncthreads();

    int   e   = t >> 2, sub = t & 3;
    int   ge  = e0 + e;
    float tte = s_dtv[e];

    float Dv[4][4][4];
    #pragma unroll
    for (int i = 0; i < 4; i++)
        #pragma unroll
        for (int jn = 0; jn < 4; jn++)
            #pragma unroll
            for (int c = 0; c < 4; c++) Dv[i][jn][c] = 0.f;

    for (int c = 0; c < 2; c++) {
        if (c > 0) __syncthreads();   // prior chunk's mma reads done

        // ---- fill A chunk: float2 loads -> split-bf16 smem ----
        int kb = sub * 48;
        #pragma unroll 4
        for (int ip = 0; ip < 24; ip++) {
            int kk = kb + 2 * ip;
            int k  = c * CHK + kk;
            float v0, v1;
            if (k < DN) {
                float2 x = *(const float2*)(h + (size_t)(NDST + ge) * DN + k);
                v0 = x.x; v1 = x.y;
            } else if (k < DN + DE) {
                float2 x = *(const float2*)(ef + (size_t)ge * DE + (k - DN));
                v0 = x.x; v1 = x.y;
            } else if (k < KV_IN) {
                int c2 = k - DN - DE;
                v0 = cosf(fmaf(tte, time_w[c2],     time_b[c2]));
                v1 = cosf(fmaf(tte, time_w[c2 + 1], time_b[c2 + 1]));
            } else { v0 = 0.f; v1 = 0.f; }
            __nv_bfloat16 h0 = __float2bfloat16(v0);
            __nv_bfloat16 h1 = __float2bfloat16(v1);
            float r0 = v0 - __bfloat162float(h0);
            float r1 = v1 - __bfloat162float(h1);
            uint32_t hi2 = (uint32_t)__bfloat16_as_ushort(h0)
                         | ((uint32_t)__bfloat16_as_ushort(h1) << 16);
            *(uint32_t*)(sAhi + e * PKA + kk) = hi2;
            *(uint32_t*)(sAlo + e * PKA + kk) = bfpack(r0, r1);
        }
        __syncthreads();

        // ---- 12 k-steps of m16n8k16, 4 jn col-groups ----
        for (int s = 0; s < 12; s++) {
            int kk = s * 16;
            int gk = c * CHK + kk;
            uint32_t bh[4][2], bl[4][2];
            #pragma unroll
            for (int jn = 0; jn < 4; jn++) {
                int n = nb + jn * 8 + g;
                const __nv_bfloat16* ph = g_BT_hi + (size_t)n * KPAD + gk + 2 * tq;
                const __nv_bfloat16* pl = g_BT_lo + (size_t)n * KPAD + gk + 2 * tq;
                bh[jn][0] = *(const uint32_t*)(ph);
                bh[jn][1] = *(const uint32_t*)(ph + 8);
                bl[jn][0] = *(const uint32_t*)(pl);
                bl[jn][1] = *(const uint32_t*)(pl + 8);
            }
            #pragma unroll
            for (int i = 0; i < 4; i++) {
                int r0 = i * 16 + g, r1 = r0 + 8;
                uint32_t ah[4], al[4];
                ah[0] = *(const uint32_t*)(sAhi + r0 * PKA + kk + 2 * tq);
                ah[1] = *(const uint32_t*)(sAhi + r1 * PKA + kk + 2 * tq);
                ah[2] = *(const uint32_t*)(sAhi + r0 * PKA + kk + 8 + 2 * tq);
                ah[3] = *(const uint32_t*)(sAhi + r1 * PKA + kk + 8 + 2 * tq);
                al[0] = *(const uint32_t*)(sAlo + r0 * PKA + kk + 2 * tq);
                al[1] = *(const uint32_t*)(sAlo + r1 * PKA + kk + 2 * tq);
                al[2] = *(const uint32_t*)(sAlo + r0 * PKA + kk + 8 + 2 * tq);
                al[3] = *(const uint32_t*)(sAlo + r1 * PKA + kk + 8 + 2 * tq);
                #pragma unroll
                for (int jn = 0; jn < 4; jn++) {
                    mma16816(Dv[i][jn], ah, bh[jn]);
                    mma16816(Dv[i][jn], al, bh[jn]);
                    mma16816(Dv[i][jn], ah, bl[jn]);
                }
            }
        }
    }

    // ---- K-warps: score partials = K-frag . Q[dst] ----
    if (wid < 4) {
        int hh = (wid >= 2) ? 1 : 0;    // cols 0..63 head0, 64..127 head1
        #pragma unroll
        for (int i = 0; i < 4; i++) {
            #pragma unroll
            for (int half = 0; half < 2; half++) {
                int r = i * 16 + g + half * 8;
                const float* qr = g_qnodes + (size_t)s_dst[r] * DOUT + nb;
                float acc = 0.f;
                #pragma unroll
                for (int jn = 0; jn < 4; jn++) {
                    float2 q2 = *(const float2*)(qr + jn * 8 + 2 * tq);
                    acc += Dv[i][jn][half * 2 + 0] * q2.x
                         + Dv[i][jn][half * 2 + 1] * q2.y;
                }
                acc += __shfl_down_sync(0xffffffffu, acc, 2, 4);
                acc += __shfl_down_sync(0xffffffffu, acc, 1, 4);
                if (tq == 0) atomicAdd(&s_sc[r][hh], acc);
            }
        }
    }
    __syncthreads();

    // ---- scores: bias folds, leaky, exp, z ----
    if (t < MT) {
        int d = s_dst[t];
        float a0 = s_sc[t][0] + s_ab[0] + g_qb[d * HEADS + 0];
        float a1 = s_sc[t][1] + s_ab[1] + g_qb[d * HEADS + 1];
        a0 = a0 > 0.f ? a0 : 0.2f * a0;
        a1 = a1 > 0.f ? a1 : 0.2f * a1;
        float w0 = expf(a0), w1 = expf(a1);
        s_w[t][0] = w0; s_w[t][1] = w1;
        atomicAdd(&g_z[d * HEADS + 0], w0);
        atomicAdd(&g_z[d * HEADS + 1], w1);
    }
    __syncthreads();

    // ---- V-warps: weighted aggregation from fragments ----
    if (wid >= 4) {
        #pragma unroll
        for (int jn = 0; jn < 4; jn++) {
            int n = (nb - DOUT) + jn * 8 + 2 * tq;   // V col
            int hh = (n >= 64) ? 1 : 0;
            float bv0 = bv[n], bv1 = bv[n + 1];
            #pragma unroll
            for (int i = 0; i < 4; i++) {
                int ea = i * 16 + g, eb = ea + 8;
                float wa = s_w[ea][hh], wb = s_w[eb][hh];
                float* pa = g_agg + (size_t)s_dst[ea] * DOUT + n;
                float* pb = g_agg + (size_t)s_dst[eb] * DOUT + n;
                atomicAdd(pa,     (Dv[i][jn][0] + bv0) * wa);
                atomicAdd(pa + 1, (Dv[i][jn][1] + bv1) * wa);
                atomicAdd(pb,     (Dv[i][jn][2] + bv0) * wb);
                atomicAdd(pb + 1, (Dv[i][jn][3] + bv1) * wb);
            }
        }
    }
}

// ---------------- output GEMM + ReLU + LayerNorm ---------------------------
__global__ __launch_bounds__(128) void k_out(
    const float* __restrict__ h,   const float* __restrict__ wout,
    const float* __restrict__ bout, const float* __restrict__ ln_g,
    const float* __restrict__ ln_b, float* __restrict__ out)
{
    int j  = threadIdx.x;
    int n0 = blockIdx.x * 4;
    __shared__ float s_row[4][OUT_IN];
    __shared__ float s_sum[4][4], s_sq[4][4];

    for (int n = 0; n < 4; n++) {
        int d = n0 + n;
        float z0 = g_z[d * HEADS + 0], z1 = g_z[d * HEADS + 1];
        float i0 = z0 > 0.f ? 1.f / z0 : 0.f;
        float i1 = z1 > 0.f ? 1.f / z1 : 0.f;
        for (int k = j; k < DOUT; k += 128)
            s_row[n][k] = g_agg[d * DOUT + k] * (k < 64 ? i0 : i1);
        for (int k = j; k < DN; k += 128)
            s_row[n][DOUT + k] = h[(size_t)d * DN + k];
    }
    __syncthreads();

    float acc[4];
    float bj = bout[j];
    #pragma unroll
    for (int n = 0; n < 4; n++) acc[n] = bj;
    for (int i = 0; i < OUT_IN; i++) {
        float w = wout[i * DOUT + j];
        #pragma unroll
        for (int n = 0; n < 4; n++) acc[n] = fmaf(s_row[n][i], w, acc[n]);
    }
    #pragma unroll
    for (int n = 0; n < 4; n++) acc[n] = acc[n] > 0.f ? acc[n] : 0.f;

    int lane = j & 31, wp = j >> 5;
    #pragma unroll
    for (int n = 0; n < 4; n++) {
        float s = acc[n], q = acc[n] * acc[n];
        #pragma unroll
        for (int o = 16; o; o >>= 1) {
            s += __shfl_down_sync(0xffffffffu, s, o);
            q += __shfl_down_sync(0xffffffffu, q, o);
        }
        if (lane == 0) { s_sum[n][wp] = s; s_sq[n][wp] = q; }
    }
    __syncthreads();

    float gj = ln_g[j], lbj = ln_b[j];
    #pragma unroll
    for (int n = 0; n < 4; n++) {
        float s = s_sum[n][0] + s_sum[n][1] + s_sum[n][2] + s_sum[n][3];
        float q = s_sq[n][0]  + s_sq[n][1]  + s_sq[n][2]  + s_sq[n][3];
        float mean = s * (1.f / DOUT);
        float var  = q * (1.f / DOUT) - mean * mean;
        float r    = rsqrtf(var + 1e-5f);
        out[(size_t)(n0 + n) * DOUT + j] = (acc[n] - mean) * r * gj + lbj;
    }
}

// ---------------- launch ----------------------------------------------------
extern "C" void kernel_launch(void* const* d_in, const int* in_sizes, int n_in,
                              void* d_out, int out_size)
{
    const float* h        = (const float*)d_in[0];
    const float* ef       = (const float*)d_in[1];
    const float* dt       = (const float*)d_in[2];
    const int*   dst_idx  = (const int*)  d_in[3];
    const float* time_w   = (const float*)d_in[5];
    const float* time_b   = (const float*)d_in[6];
    const float* wq       = (const float*)d_in[7];
    const float* bq       = (const float*)d_in[8];
    const float* wk       = (const float*)d_in[9];
    const float* bk       = (const float*)d_in[10];
    const float* wv       = (const float*)d_in[11];
    const float* bv       = (const float*)d_in[12];
    const float* att_bias = (const float*)d_in[13];
    const float* wout     = (const float*)d_in[14];
    const float* bout     = (const float*)d_in[15];
    const float* ln_g     = (const float*)d_in[16];
    const float* ln_b     = (const float*)d_in[17];
    float* out = (float*)d_out;

    static int smem_set = 0;
    if (!smem_set) {
        cudaFuncSetAttribute(k_edge, cudaFuncAttributeMaxDynamicSharedMemorySize,
                             SMEM_EDGE_BYTES);
        smem_set = 1;
    }

    k_init<<<512, 256>>>();
    k_prepB<<<(NB * KPAD + 255) / 256, 256>>>(wk, wv);
    k_qnodes<<<NDST / 4, 128>>>(h, wq, bq, time_b);
    k_qb<<<(NDST * HEADS + 255) / 256, 256>>>(bk);
    k_edge<<<NBLK, 256, SMEM_EDGE_BYTES>>>(
        h, ef, dt, dst_idx, time_w, time_b, bv, att_bias);
    k_out<<<NDST / 4, 128>>>(h, wout, bout, ln_g, ln_b, out);
}

// round 14
// speedup vs baseline: 1.2842x; 1.2842x over previous
#include <cuda_runtime.h>
#include <cuda_bf16.h>
#include <math.h>
#include <stdint.h>

// ---------------- problem constants ----------------------------------------
#define E_TOTAL 600000
#define NDST    10000
#define DN      100
#define DE      172
#define DTF     100
#define DOUT    128
#define HEADS   2
#define KV_IN   372   // DN + DE + DTF
#define KPAD    384
#define OUT_IN  228   // DOUT + DN
#define QWROW   (KV_IN * HEADS)   // 744
#define QWN     8
#define MT      64    // edges per block in k_edge
#define NBLK    (E_TOTAL / MT)    // 9375
#define CHK     192   // k per chunk
#define PKA     200   // A smem pitch (bf16 elems): 400B rows -> bank-shift 4
#define SMEM_EDGE_BYTES (MT * PKA * 2 * 2)   // hi+lo planes = 51200 B

// ---------------- scratch (device globals) ---------------------------------
__device__ float g_qnodes[NDST * DOUT];
__device__ float g_qw[NDST * QWROW];  // QW[d][k][h]
__device__ float g_qb[NDST * HEADS];  // fold of bk into Q
__device__ float g_z[NDST * HEADS];
__device__ float g_agg[NDST * DOUT];
__device__ float g_wkT[DOUT * KV_IN]; // wk transposed [j][k] for coalesced k_qw
// wv transposed [n][k] split-bf16 (k padded to 384)
__device__ __nv_bfloat16 g_BT_hi[DOUT * KPAD];
__device__ __nv_bfloat16 g_BT_lo[DOUT * KPAD];

// ---------------- helpers ---------------------------------------------------
__device__ __forceinline__ uint32_t smem_u32(const void* p) {
    uint32_t a;
    asm("{ .reg .u64 t; cvta.to.shared.u64 t, %1; cvt.u32.u64 %0, t; }"
        : "=r"(a) : "l"(p));
    return a;
}
__device__ __forceinline__ void mma16816(float* c, const uint32_t* a,
                                         const uint32_t* b) {
    asm volatile(
        "mma.sync.aligned.m16n8k16.row.col.f32.bf16.bf16.f32 "
        "{%0,%1,%2,%3}, {%4,%5,%6,%7}, {%8,%9}, {%0,%1,%2,%3};"
        : "+f"(c[0]), "+f"(c[1]), "+f"(c[2]), "+f"(c[3])
        : "r"(a[0]), "r"(a[1]), "r"(a[2]), "r"(a[3]), "r"(b[0]), "r"(b[1]));
}
__device__ __forceinline__ void ldsm_x4(uint32_t* r, uint32_t addr) {
    asm volatile("ldmatrix.sync.aligned.m8n8.x4.shared.b16 {%0,%1,%2,%3}, [%4];"
        : "=r"(r[0]), "=r"(r[1]), "=r"(r[2]), "=r"(r[3]) : "r"(addr));
}
__device__ __forceinline__ uint32_t bfpack(float v0, float v1) {
    __nv_bfloat16 h0 = __float2bfloat16(v0), h1 = __float2bfloat16(v1);
    return (uint32_t)__bfloat16_as_ushort(h0)
         | ((uint32_t)__bfloat16_as_ushort(h1) << 16);
}

// ---------------- init ------------------------------------------------------
__global__ void k_init() {
    int i = blockIdx.x * blockDim.x + threadIdx.x;
    int stride = gridDim.x * blockDim.x;
    for (int k = i; k < NDST * HEADS; k += stride) g_z[k] = 0.f;
    for (int k = i; k < NDST * DOUT; k += stride)  g_agg[k] = 0.f;
}

// ---------------- prep B: wv -> transposed split-bf16; wk -> transpose -----
__global__ void k_prepB(const float* __restrict__ wk, const float* __restrict__ wv) {
    int i = blockIdx.x * blockDim.x + threadIdx.x;
    if (i < DOUT * KPAD) {
        int n = i / KPAD, k = i % KPAD;
        float v = (k < KV_IN) ? wv[k * DOUT + n] : 0.f;
        __nv_bfloat16 hi = __float2bfloat16(v);
        g_BT_hi[i] = hi;
        g_BT_lo[i] = __float2bfloat16(v - __bfloat162float(hi));
    }
    if (i < DOUT * KV_IN) {
        int j = i / KV_IN, k = i % KV_IN;
        g_wkT[i] = wk[k * DOUT + j];
    }
}

// ---------------- Q per dst node -------------------------------------------
__global__ __launch_bounds__(128) void k_qnodes(
    const float* __restrict__ h, const float* __restrict__ wq,
    const float* __restrict__ bq, const float* __restrict__ time_b)
{
    int j  = threadIdx.x;
    int n0 = blockIdx.x * 4;
    __shared__ float sh[4][DN];
    for (int idx = j; idx < 4 * DN; idx += 128) {
        int n = idx / DN, i = idx % DN;
        sh[n][i] = h[(size_t)(n0 + n) * DN + i];
    }
    __syncthreads();
    float qc = bq[j];
    for (int i = 0; i < DTF; i++)
        qc = fmaf(wq[(DN + i) * DOUT + j], cosf(time_b[i]), qc);
    float a0 = qc, a1 = qc, a2 = qc, a3 = qc;
    for (int i = 0; i < DN; i++) {
        float w = wq[i * DOUT + j];
        a0 = fmaf(sh[0][i], w, a0);
        a1 = fmaf(sh[1][i], w, a1);
        a2 = fmaf(sh[2][i], w, a2);
        a3 = fmaf(sh[3][i], w, a3);
    }
    g_qnodes[(n0 + 0) * DOUT + j] = a0;
    g_qnodes[(n0 + 1) * DOUT + j] = a1;
    g_qnodes[(n0 + 2) * DOUT + j] = a2;
    g_qnodes[(n0 + 3) * DOUT + j] = a3;
}

// ---------------- QW table (coalesced via wkT) -----------------------------
// QW[d][k][h] = sum_{j<64} q[d][h*64+j] * wkT[h*64+j][k]
__global__ __launch_bounds__(128) void k_qw() {
    int n0 = blockIdx.x * QWN;
    __shared__ float sq[QWN][DOUT];
    for (int idx = threadIdx.x; idx < QWN * DOUT; idx += 128) {
        int n = idx >> 7, j = idx & 127;
        sq[n][j] = g_qnodes[(size_t)(n0 + n) * DOUT + j];
    }
    __syncthreads();
    for (int k = threadIdx.x; k < KV_IN; k += 128) {
        #pragma unroll
        for (int hh = 0; hh < HEADS; hh++) {
            float a[QWN];
            #pragma unroll
            for (int n = 0; n < QWN; n++) a[n] = 0.f;
            for (int j = 0; j < 64; j++) {
                float w = g_wkT[(size_t)(hh * 64 + j) * KV_IN + k];  // coalesced
                #pragma unroll
                for (int n = 0; n < QWN; n++)
                    a[n] = fmaf(sq[n][hh * 64 + j], w, a[n]);
            }
            #pragma unroll
            for (int n = 0; n < QWN; n++)
                g_qw[(size_t)(n0 + n) * QWROW + k * HEADS + hh] = a[n];
        }
    }
}

// ---------------- fold bk into per-(dst,head) score constant ---------------
__global__ void k_qb(const float* __restrict__ bk) {
    int i = blockIdx.x * blockDim.x + threadIdx.x;
    if (i >= NDST * HEADS) return;
    int d = i >> 1, hh = i & 1;
    float s = 0.f;
    for (int j = 0; j < 64; j++)
        s = fmaf(g_qnodes[(size_t)d * DOUT + hh * 64 + j], bk[hh * 64 + j], s);
    g_qb[i] = s;
}

// ---------------- HMMA edge kernel -----------------------------------------
// V[64x128] = X[64x384] * wv via split-bf16 mma.sync (3 terms), A frags via
// ldmatrix.x4. Scores in fp32 during the fill (QW trick), exp w/o max-sub,
// z/agg via L2 atomics.
__global__ __launch_bounds__(256, 2) void k_edge(
    const float* __restrict__ h,  const float* __restrict__ ef,
    const float* __restrict__ dt, const int*   __restrict__ dst_idx,
    const float* __restrict__ time_w, const float* __restrict__ time_b,
    const float* __restrict__ bv, const float* __restrict__ att_bias)
{
    extern __shared__ unsigned char dsm[];
    __nv_bfloat16* sAhi = (__nv_bfloat16*)dsm;               // [MT][PKA]
    __nv_bfloat16* sAlo = sAhi + MT * PKA;
    __shared__ int   s_dst[MT];
    __shared__ float s_dtv[MT];
    __shared__ float s_w[MT][HEADS];
    __shared__ float s_ab[2];

    int t   = threadIdx.x;
    int e0  = blockIdx.x * MT;
    int wid = t >> 5, lane = t & 31;
    int g   = lane >> 2, tq = lane & 3;
    int n0  = wid * 16;

    if (t < MT) { s_dst[t] = dst_idx[e0 + t]; s_dtv[t] = dt[e0 + t]; }
    if (t < 2) {
        float s = 0.f;
        #pragma unroll 8
        for (int i = 0; i < 64; i++) s += att_bias[t * 64 + i];
        s_ab[t] = s;
    }
    __syncthreads();

    int   e   = t >> 2, sub = t & 3;
    int   ge  = e0 + e;
    int   d_e = s_dst[e];
    float tte = s_dtv[e];
    const float* qwr = g_qw + (size_t)d_e * QWROW;

    // ldmatrix per-lane base offsets (elements)
    uint32_t sAhi_u = smem_u32(sAhi);
    uint32_t sAlo_u = smem_u32(sAlo);
    uint32_t lmoff  = (uint32_t)(lane & 15) * PKA + ((lane >> 4) << 3);

    float Dv[4][2][4];
    #pragma unroll
    for (int i = 0; i < 4; i++)
        #pragma unroll
        for (int jn = 0; jn < 2; jn++)
            #pragma unroll
            for (int c = 0; c < 4; c++) Dv[i][jn][c] = 0.f;

    float sc0 = 0.f, sc1 = 0.f;

    for (int c = 0; c < 2; c++) {
        if (c > 0) __syncthreads();   // prior chunk's mma reads done

        // ---- fill A chunk: fp32 x -> score partials + split-bf16 smem ----
        int kb = sub * 48;
        for (int i = 0; i < 48; i++) {
            int kk = kb + i;
            int k  = c * CHK + kk;
            float v = 0.f;
            if (k < DN)            v = h[(size_t)(NDST + ge) * DN + k];
            else if (k < DN + DE)  v = ef[(size_t)ge * DE + (k - DN)];
            else if (k < KV_IN)    v = cosf(fmaf(tte, time_w[k - DN - DE],
                                                 time_b[k - DN - DE]));
            if (k < KV_IN) {
                float2 q2 = *(const float2*)(qwr + k * 2);
                sc0 = fmaf(v, q2.x, sc0);
                sc1 = fmaf(v, q2.y, sc1);
            }
            __nv_bfloat16 hi = __float2bfloat16(v);
            sAhi[e * PKA + kk] = hi;
            sAlo[e * PKA + kk] = __float2bfloat16(v - __bfloat162float(hi));
        }
        __syncthreads();

        // ---- 12 k-steps of m16n8k16 ----
        for (int s = 0; s < 12; s++) {
            int kk = s * 16;
            int gk = c * CHK + kk;
            uint32_t bh[2][2], bl[2][2];
            #pragma unroll
            for (int jn = 0; jn < 2; jn++) {
                int n = n0 + jn * 8 + g;
                const __nv_bfloat16* ph = g_BT_hi + (size_t)n * KPAD + gk + 2 * tq;
                const __nv_bfloat16* pl = g_BT_lo + (size_t)n * KPAD + gk + 2 * tq;
                bh[jn][0] = *(const uint32_t*)(ph);
                bh[jn][1] = *(const uint32_t*)(ph + 8);
                bl[jn][0] = *(const uint32_t*)(pl);
                bl[jn][1] = *(const uint32_t*)(pl + 8);
            }
            #pragma unroll
            for (int i = 0; i < 4; i++) {
                uint32_t off = (uint32_t)(i * 16) * PKA + kk + lmoff;
                uint32_t ah[4], al[4];
                ldsm_x4(ah, sAhi_u + off * 2);
                ldsm_x4(al, sAlo_u + off * 2);
                #pragma unroll
                for (int jn = 0; jn < 2; jn++) {
                    mma16816(Dv[i][jn], ah, bh[jn]);
                    mma16816(Dv[i][jn], al, bh[jn]);
                    mma16816(Dv[i][jn], ah, bl[jn]);
                }
            }
        }
    }

    // ---- scores: reduce 4-lane partials, leaky, exp, z ----
    sc0 += __shfl_down_sync(0xffffffffu, sc0, 2, 4);
    sc0 += __shfl_down_sync(0xffffffffu, sc0, 1, 4);
    sc1 += __shfl_down_sync(0xffffffffu, sc1, 2, 4);
    sc1 += __shfl_down_sync(0xffffffffu, sc1, 1, 4);
    if (sub == 0) {
        float a0 = sc0 + s_ab[0] + g_qb[d_e * HEADS + 0];
        float a1 = sc1 + s_ab[1] + g_qb[d_e * HEADS + 1];
        a0 = a0 > 0.f ? a0 : 0.2f * a0;
        a1 = a1 > 0.f ? a1 : 0.2f * a1;
        float w0 = expf(a0), w1 = expf(a1);
        s_w[e][0] = w0; s_w[e][1] = w1;
        atomicAdd(&g_z[d_e * HEADS + 0], w0);
        atomicAdd(&g_z[d_e * HEADS + 1], w1);
    }
    __syncthreads();

    // ---- weighted aggregation from fragments ----
    int hh = wid >> 2;   // cols [0,64) head 0, [64,128) head 1
    #pragma unroll
    for (int jn = 0; jn < 2; jn++) {
        int n = n0 + jn * 8 + 2 * tq;
        float bv0 = bv[n], bv1 = bv[n + 1];
        #pragma unroll
        for (int i = 0; i < 4; i++) {
            int ea = i * 16 + g, eb = ea + 8;
            float wa = s_w[ea][hh], wb = s_w[eb][hh];
            float* pa = g_agg + (size_t)s_dst[ea] * DOUT + n;
            float* pb = g_agg + (size_t)s_dst[eb] * DOUT + n;
            atomicAdd(pa,     (Dv[i][jn][0] + bv0) * wa);
            atomicAdd(pa + 1, (Dv[i][jn][1] + bv1) * wa);
            atomicAdd(pb,     (Dv[i][jn][2] + bv0) * wb);
            atomicAdd(pb + 1, (Dv[i][jn][3] + bv1) * wb);
        }
    }
}

// ---------------- output GEMM + ReLU + LayerNorm ---------------------------
__global__ __launch_bounds__(128) void k_out(
    const float* __restrict__ h,   const float* __restrict__ wout,
    const float* __restrict__ bout, const float* __restrict__ ln_g,
    const float* __restrict__ ln_b, float* __restrict__ out)
{
    int j  = threadIdx.x;
    int n0 = blockIdx.x * 4;
    __shared__ float s_row[4][OUT_IN];
    __shared__ float s_sum[4][4], s_sq[4][4];

    for (int n = 0; n < 4; n++) {
        int d = n0 + n;
        float z0 = g_z[d * HEADS + 0], z1 = g_z[d * HEADS + 1];
        float i0 = z0 > 0.f ? 1.f / z0 : 0.f;
        float i1 = z1 > 0.f ? 1.f / z1 : 0.f;
        for (int k = j; k < DOUT; k += 128)
            s_row[n][k] = g_agg[d * DOUT + k] * (k < 64 ? i0 : i1);
        for (int k = j; k < DN; k += 128)
            s_row[n][DOUT + k] = h[(size_t)d * DN + k];
    }
    __syncthreads();

    float acc[4];
    float bj = bout[j];
    #pragma unroll
    for (int n = 0; n < 4; n++) acc[n] = bj;
    for (int i = 0; i < OUT_IN; i++) {
        float w = wout[i * DOUT + j];
        #pragma unroll
        for (int n = 0; n < 4; n++) acc[n] = fmaf(s_row[n][i], w, acc[n]);
    }
    #pragma unroll
    for (int n = 0; n < 4; n++) acc[n] = acc[n] > 0.f ? acc[n] : 0.f;

    int lane = j & 31, wp = j >> 5;
    #pragma unroll
    for (int n = 0; n < 4; n++) {
        float s = acc[n], q = acc[n] * acc[n];
        #pragma unroll
        for (int o = 16; o; o >>= 1) {
            s += __shfl_down_sync(0xffffffffu, s, o);
            q += __shfl_down_sync(0xffffffffu, q, o);
        }
        if (lane == 0) { s_sum[n][wp] = s; s_sq[n][wp] = q; }
    }
    __syncthreads();

    float gj = ln_g[j], lbj = ln_b[j];
    #pragma unroll
    for (int n = 0; n < 4; n++) {
        float s = s_sum[n][0] + s_sum[n][1] + s_sum[n][2] + s_sum[n][3];
        float q = s_sq[n][0]  + s_sq[n][1]  + s_sq[n][2]  + s_sq[n][3];
        float mean = s * (1.f / DOUT);
        float var  = q * (1.f / DOUT) - mean * mean;
        float r    = rsqrtf(var + 1e-5f);
        out[(size_t)(n0 + n) * DOUT + j] = (acc[n] - mean) * r * gj + lbj;
    }
}

// ---------------- launch ----------------------------------------------------
extern "C" void kernel_launch(void* const* d_in, const int* in_sizes, int n_in,
                              void* d_out, int out_size)
{
    const float* h        = (const float*)d_in[0];
    const float* ef       = (const float*)d_in[1];
    const float* dt       = (const float*)d_in[2];
    const int*   dst_idx  = (const int*)  d_in[3];
    const float* time_w   = (const float*)d_in[5];
    const float* time_b   = (const float*)d_in[6];
    const float* wq       = (const float*)d_in[7];
    const float* bq       = (const float*)d_in[8];
    const float* wk       = (const float*)d_in[9];
    const float* bk       = (const float*)d_in[10];
    const float* wv       = (const float*)d_in[11];
    const float* bv       = (const float*)d_in[12];
    const float* att_bias = (const float*)d_in[13];
    const float* wout     = (const float*)d_in[14];
    const float* bout     = (const float*)d_in[15];
    const float* ln_g     = (const float*)d_in[16];
    const float* ln_b     = (const float*)d_in[17];
    float* out = (float*)d_out;

    static int smem_set = 0;
    if (!smem_set) {
        cudaFuncSetAttribute(k_edge, cudaFuncAttributeMaxDynamicSharedMemorySize,
                             SMEM_EDGE_BYTES);
        smem_set = 1;
    }

    k_init<<<512, 256>>>();
    k_prepB<<<(DOUT * KPAD + 255) / 256, 256>>>(wk, wv);
    k_qnodes<<<NDST / 4, 128>>>(h, wq, bq, time_b);
    k_qw<<<NDST / QWN, 128>>>();
    k_qb<<<(NDST * HEADS + 255) / 256, 256>>>(bk);
    k_edge<<<NBLK, 256, SMEM_EDGE_BYTES>>>(
        h, ef, dt, dst_idx, time_w, time_b, bv, att_bias);
    k_out<<<NDST / 4, 128>>>(h, wout, bout, ln_g, ln_b, out);
}